// round 2
// baseline (speedup 1.0000x reference)
#include <cuda_runtime.h>

#define NT 256
#define BT 8

typedef unsigned long long u64;

// ---------------- packed f32x2 helpers ----------------
__device__ __forceinline__ void ffma2(u64 &acc, u64 a, u64 w) {
    asm("fma.rn.f32x2 %0, %1, %2, %0;" : "+l"(acc) : "l"(a), "l"(w));
}
__device__ __forceinline__ float sum2(u64 v) {
    return __uint_as_float((unsigned int)v) + __uint_as_float((unsigned int)(v >> 32));
}

// ---------------- activations ----------------
__device__ __forceinline__ float softplus_f(float x) {
    float r = __logf(1.f + __expf(x));
    return (x > 15.f) ? x : r;
}
__device__ __forceinline__ float tanh_f(float x) {
    float xx = fminf(fmaxf(x, -12.f), 12.f);
    float e = __expf(2.f * xx);
    return (e - 1.f) * __fdividef(1.f, e + 1.f);
}

// ---------------- vw3 in k-major quad-interleaved layout ----------------
// g_vw3q[(k>>2)*2048 + c*4 + (k&3)] = vw3[c*128 + k],  c in [0,512), k in [0,128)
__device__ float g_vw3q[512 * 128];

__global__ void prep_vw3(const float* __restrict__ vw3) {
    int id = blockIdx.x * blockDim.x + threadIdx.x;   // 65536
    int c = id >> 7;
    int k = id & 127;
    g_vw3q[(k >> 2) * 2048 + (c << 2) + (k & 3)] = vw3[id];
}

// ---------------- smem layout (floats) ----------------
#define OFF_W1 0          // 128 x 68
#define OFF_W2 8704       // 128 x 132
#define OFF_B1 25600      // 128
#define OFF_B2 25728      // 128
#define OFF_B3 25856      // 512
#define OFF_LW 26368      // 64
#define OFF_Y  26432      // 8 x 64
#define OFF_YT 26944      // 8 x 64
#define OFF_H1 27456      // 8 x 128
#define OFF_H2 28480      // 8 x 128
#define OFF_K  29504      // 6 x 512
#define OFF_DX 32576      // 8 x 8
#define SMEM_FLOATS 32640
#define SMEM_BYTES (SMEM_FLOATS * 4)

enum { ACT_ID = 0, ACT_RELU = 1, ACT_SP = 2 };

// OUT[8][C] = act( ACTS[8][K] @ W[C][K]^T + bias ),  W padded to stride WS in smem.
template<int C, int K, int WS, int ACT>
__device__ __forceinline__ void dense(const float* __restrict__ wp,
                                      const float* __restrict__ bias,
                                      const float* __restrict__ actbuf,
                                      float* __restrict__ outp, int tid) {
    constexpr int RPT = (8 * C) / NT;            // 4 for C=128, 2 for C=64
    const int c  = tid % C;
    const int r0 = (tid / C) * RPT;
    u64 acc[RPT][2];
#pragma unroll
    for (int i = 0; i < RPT; i++) { acc[i][0] = 0ull; acc[i][1] = 0ull; }
    const float* wr = wp + c * WS;
#pragma unroll 8
    for (int k = 0; k < K; k += 4) {
        ulonglong2 w = *(const ulonglong2*)(wr + k);
#pragma unroll
        for (int i = 0; i < RPT; i++) {
            ulonglong2 a = *(const ulonglong2*)(actbuf + (r0 + i) * K + k);
            ffma2(acc[i][0], a.x, w.x);
            ffma2(acc[i][1], a.y, w.y);
        }
    }
    float b = bias[c];
#pragma unroll
    for (int i = 0; i < RPT; i++) {
        float v = sum2(acc[i][0]) + sum2(acc[i][1]) + b;
        if (ACT == ACT_RELU) v = fmaxf(v, 0.f);
        if (ACT == ACT_SP)   v = softplus_f(v);
        outp[(r0 + i) * C + c] = v;
    }
}

// L3 (512 outs, K=128) + tanh + einsum with dx -> kout[8][64]
// thread owns columns c0=tid and c1=tid+256 for all 8 rows.
__device__ __forceinline__ void l3contract(const float* __restrict__ h2s,
                                           const float* __restrict__ b3s,
                                           const float* __restrict__ dxs,
                                           float* __restrict__ kout, int tid) {
    u64 acc0[8], acc1[8];
#pragma unroll
    for (int r = 0; r < 8; r++) { acc0[r] = 0ull; acc1[r] = 0ull; }
#pragma unroll 8
    for (int k = 0; k < 128; k += 4) {
        const float* p = g_vw3q + (k >> 2) * 2048 + tid * 4;
        ulonglong2 w0 = *(const ulonglong2*)(p);          // col tid,     k..k+3
        ulonglong2 w1 = *(const ulonglong2*)(p + 1024);   // col tid+256, k..k+3
#pragma unroll
        for (int r = 0; r < 8; r++) {
            ulonglong2 a = *(const ulonglong2*)(h2s + r * 128 + k);
            ffma2(acc0[r], a.x, w0.x);
            ffma2(acc0[r], a.y, w0.y);
            ffma2(acc1[r], a.x, w1.x);
            ffma2(acc1[r], a.y, w1.y);
        }
    }
    const int h0 = tid >> 3;            // 0..31
    const int d  = tid & 7;
    const float b0 = b3s[tid];
    const float b1 = b3s[tid + 256];
#pragma unroll
    for (int r = 0; r < 8; r++) {
        float f0 = tanh_f(sum2(acc0[r]) + b0);
        float f1 = tanh_f(sum2(acc1[r]) + b1);
        float dxv = dxs[r * 8 + d];
        float pa = f0 * dxv;
        float pb = f1 * dxv;
        pa += __shfl_xor_sync(0xffffffffu, pa, 1);
        pa += __shfl_xor_sync(0xffffffffu, pa, 2);
        pa += __shfl_xor_sync(0xffffffffu, pa, 4);
        pb += __shfl_xor_sync(0xffffffffu, pb, 1);
        pb += __shfl_xor_sync(0xffffffffu, pb, 2);
        pb += __shfl_xor_sync(0xffffffffu, pb, 4);
        if (d == 0) {
            kout[r * 64 + h0]      = pa;
            kout[r * 64 + h0 + 32] = pb;
        }
    }
}

__device__ __forceinline__ void vf(const float* __restrict__ ysrc, float* __restrict__ kout,
                                   const float* w1p, const float* b1s,
                                   const float* w2p, const float* b2s,
                                   const float* b3s, const float* dxs,
                                   float* h1, float* h2, int tid) {
    dense<128, 64, 68, ACT_SP>(w1p, b1s, ysrc, h1, tid);
    __syncthreads();
    dense<128, 128, 132, ACT_SP>(w2p, b2s, h1, h2, tid);
    __syncthreads();
    l3contract(h2, b3s, dxs, kout, tid);
    __syncthreads();
}

__device__ __forceinline__ void write_out(const float* __restrict__ y,
                                          const float* __restrict__ lws, float lbv,
                                          float* __restrict__ out, int b0, int t, int tid) {
    int w = tid >> 5, l = tid & 31;           // warp w handles batch row w
    float p = y[w * 64 + l] * lws[l] + y[w * 64 + 32 + l] * lws[32 + l];
#pragma unroll
    for (int s = 16; s > 0; s >>= 1) p += __shfl_xor_sync(0xffffffffu, p, s);
    if (l == 0) {
        float z = p + lbv;
        out[(b0 + w) * 64 + t] = __fdividef(1.f, 1.f + __expf(-z));
    }
}

__global__ void __launch_bounds__(NT, 1)
cde_kernel(const float* __restrict__ ts, const float* __restrict__ xs,
           const float* __restrict__ iw1, const float* __restrict__ ib1,
           const float* __restrict__ iw2, const float* __restrict__ ib2,
           const float* __restrict__ iw3, const float* __restrict__ ib3,
           const float* __restrict__ vw1, const float* __restrict__ vb1,
           const float* __restrict__ vw2, const float* __restrict__ vb2,
           const float* __restrict__ vb3,
           const float* __restrict__ lw, const float* __restrict__ lb,
           float* __restrict__ out) {
    extern __shared__ float sm[];
    const int tid = threadIdx.x;
    const int b0 = blockIdx.x * BT;

    float* w1p = sm + OFF_W1;
    float* w2p = sm + OFF_W2;
    float* b1s = sm + OFF_B1;
    float* b2s = sm + OFF_B2;
    float* b3s = sm + OFF_B3;
    float* lws = sm + OFF_LW;
    float* ybuf = sm + OFF_Y;
    float* yts = sm + OFF_YT;
    float* h1 = sm + OFF_H1;
    float* h2 = sm + OFF_H2;
    float* ksb = sm + OFF_K;
    float* dxs = sm + OFF_DX;

    // ---------- initial MLP: y0 = relu-MLP(xs[:,0]) ----------
    for (int i = tid; i < 128 * 8; i += NT)   w1p[(i >> 3) * 68 + (i & 7)] = iw1[i];
    for (int i = tid; i < 128 * 128; i += NT) w2p[(i >> 7) * 132 + (i & 127)] = iw2[i];
    for (int i = tid; i < 128; i += NT) { b1s[i] = ib1[i]; b2s[i] = ib2[i]; }
    if (tid < 64) lws[tid] = lw[tid];
    if (tid < 64) {
        int r = tid >> 3, d = tid & 7;
        dxs[tid] = xs[(b0 + r) * 512 + d];          // X(t0) staged in dxs buffer
    }
    __syncthreads();
    dense<128, 8, 68, ACT_RELU>(w1p, b1s, dxs, h1, tid);
    __syncthreads();
    dense<128, 128, 132, ACT_RELU>(w2p, b2s, h1, h2, tid);
    __syncthreads();
    for (int i = tid; i < 64 * 128; i += NT)  w2p[(i >> 7) * 132 + (i & 127)] = iw3[i];
    __syncthreads();
    dense<64, 128, 132, ACT_ID>(w2p, ib3, h2, ybuf, tid);
    __syncthreads();

    // ---------- load vector-field weights ----------
    for (int i = tid; i < 128 * 64; i += NT)  w1p[(i >> 6) * 68 + (i & 63)] = vw1[i];
    for (int i = tid; i < 128 * 128; i += NT) w2p[(i >> 7) * 132 + (i & 127)] = vw2[i];
    for (int i = tid; i < 128; i += NT) { b1s[i] = vb1[i]; b2s[i] = vb2[i]; }
    for (int i = tid; i < 512; i += NT) b3s[i] = vb3[i];
    const float lbv = lb[0];
    __syncthreads();

    write_out(ybuf, lws, lbv, out, b0, 0, tid);
    __syncthreads();

    // Tsit5 coefficients
    const float A21 = 0.161f;
    const float A31 = -0.008480655492356989f, A32 = 0.335480655492357f;
    const float A41 = 2.8971530571054935f, A42 = -6.359448489975075f, A43 = 4.3622954328695815f;
    const float A51 = 5.325864828439257f, A52 = -11.748883564062828f, A53 = 7.4955393428898365f, A54 = -0.09249506636175525f;
    const float A61 = 5.86145544294642f, A62 = -12.92096931784711f, A63 = 8.159367898576159f, A64 = -0.071584973281401f, A65 = -0.028269050394068383f;
    const float B1 = 0.09646076681806523f, B2 = 0.01f, B3 = 0.4798896504144996f;
    const float B4 = 1.379008574103742f, B5 = -3.290069515436081f, B6 = 2.324710524099774f;

    float* k1 = ksb;
    float* k2 = ksb + 512;
    float* k3 = ksb + 1024;
    float* k4 = ksb + 1536;
    float* k5 = ksb + 2048;
    float* k6 = ksb + 2560;

    for (int t = 0; t < 63; t++) {
        const float dt = ts[t + 1] - ts[t];
        if (tid < 64) {
            int r = tid >> 3, d = tid & 7;
            int ix = (b0 + r) * 512 + t * 8 + d;
            dxs[tid] = (xs[ix + 8] - xs[ix]) / dt;
        }
        __syncthreads();

        // stage 1
        vf(ybuf, k1, w1p, b1s, w2p, b2s, b3s, dxs, h1, h2, tid);
        // stage 2
#pragma unroll
        for (int e = tid; e < 512; e += NT)
            yts[e] = ybuf[e] + dt * (A21 * k1[e]);
        __syncthreads();
        vf(yts, k2, w1p, b1s, w2p, b2s, b3s, dxs, h1, h2, tid);
        // stage 3
#pragma unroll
        for (int e = tid; e < 512; e += NT)
            yts[e] = ybuf[e] + dt * (A31 * k1[e] + A32 * k2[e]);
        __syncthreads();
        vf(yts, k3, w1p, b1s, w2p, b2s, b3s, dxs, h1, h2, tid);
        // stage 4
#pragma unroll
        for (int e = tid; e < 512; e += NT)
            yts[e] = ybuf[e] + dt * (A41 * k1[e] + A42 * k2[e] + A43 * k3[e]);
        __syncthreads();
        vf(yts, k4, w1p, b1s, w2p, b2s, b3s, dxs, h1, h2, tid);
        // stage 5
#pragma unroll
        for (int e = tid; e < 512; e += NT)
            yts[e] = ybuf[e] + dt * (A51 * k1[e] + A52 * k2[e] + A53 * k3[e] + A54 * k4[e]);
        __syncthreads();
        vf(yts, k5, w1p, b1s, w2p, b2s, b3s, dxs, h1, h2, tid);
        // stage 6
#pragma unroll
        for (int e = tid; e < 512; e += NT)
            yts[e] = ybuf[e] + dt * (A61 * k1[e] + A62 * k2[e] + A63 * k3[e] + A64 * k4[e] + A65 * k5[e]);
        __syncthreads();
        vf(yts, k6, w1p, b1s, w2p, b2s, b3s, dxs, h1, h2, tid);

        // y update
#pragma unroll
        for (int e = tid; e < 512; e += NT)
            ybuf[e] = ybuf[e] + dt * (B1 * k1[e] + B2 * k2[e] + B3 * k3[e]
                                    + B4 * k4[e] + B5 * k5[e] + B6 * k6[e]);
        __syncthreads();
        write_out(ybuf, lws, lbv, out, b0, t + 1, tid);
        __syncthreads();
    }
}

extern "C" void kernel_launch(void* const* d_in, const int* in_sizes, int n_in,
                              void* d_out, int out_size) {
    const float* ts  = (const float*)d_in[0];
    const float* xs  = (const float*)d_in[1];
    const float* iw1 = (const float*)d_in[2];
    const float* ib1 = (const float*)d_in[3];
    const float* iw2 = (const float*)d_in[4];
    const float* ib2 = (const float*)d_in[5];
    const float* iw3 = (const float*)d_in[6];
    const float* ib3 = (const float*)d_in[7];
    const float* vw1 = (const float*)d_in[8];
    const float* vb1 = (const float*)d_in[9];
    const float* vw2 = (const float*)d_in[10];
    const float* vb2 = (const float*)d_in[11];
    const float* vw3 = (const float*)d_in[12];
    const float* vb3 = (const float*)d_in[13];
    const float* lw  = (const float*)d_in[14];
    const float* lb  = (const float*)d_in[15];
    float* out = (float*)d_out;

    prep_vw3<<<256, 256>>>(vw3);

    cudaFuncSetAttribute(cde_kernel, cudaFuncAttributeMaxDynamicSharedMemorySize, SMEM_BYTES);
    cde_kernel<<<128, NT, SMEM_BYTES>>>(ts, xs, iw1, ib1, iw2, ib2, iw3, ib3,
                                        vw1, vb1, vw2, vb2, vb3, lw, lb, out);
}